// round 2
// baseline (speedup 1.0000x reference)
#include <cuda_runtime.h>
#include <cuda_bf16.h>

// DiagPooling: x [B=8, C=128, H=512, W=512] fp32 -> out [B, 1, 513] fp32
// out[b, 0, o] = (1 / (C * (H - |o-256|))) * sum_{c, i} x[b, c, i, i + o - 256]
//
// Only pixels with |j - i| <= 256 contribute. Row i's valid columns are
// [j0, j1] with width w(i) = 257 + min(i, 511-i) in [257, 512].
//
// Mapping: block = (i, b, c_slice), 256 threads. Thread t handles column
// j0+t (always valid, since w >= 257) and column j0+t+256 (predicated).
// Each block sums 32 channels; 4 c-slices accumulate into d_out via
// pre-scaled atomicAdd (REDG). Grid = 16384 short blocks -> negligible
// wave tail, near-100% active lanes.

#define B_DIM 8
#define C_DIM 128
#define H_DIM 512
#define W_DIM 512
#define N_OFF 513
#define OUT_ELEMS (B_DIM * N_OFF)
#define C_SLICES 4
#define C_PER_SLICE (C_DIM / C_SLICES)   // 32

__global__ void zero_out_kernel(float* __restrict__ out, int n) {
    int idx = blockIdx.x * blockDim.x + threadIdx.x;
    if (idx < n) out[idx] = 0.0f;
}

__global__ __launch_bounds__(256) void diag_pool_kernel(
    const float* __restrict__ x, float* __restrict__ out)
{
    const int i  = blockIdx.x;           // row 0..511
    const int b  = blockIdx.y;           // batch 0..7
    const int cs = blockIdx.z;           // channel slice 0..3
    const int t  = threadIdx.x;          // 0..255

    // Valid column range for this row: |j - i| <= 256
    const int j0 = (i - 256 > 0) ? (i - 256) : 0;
    const int j1 = (i + 256 < H_DIM - 1) ? (i + 256) : (H_DIM - 1);

    const int ja = j0 + t;               // always valid (min width 257)
    const int jb = ja + 256;             // valid iff jb <= j1
    const bool hasb = (jb <= j1);

    const size_t ch_stride = (size_t)H_DIM * W_DIM;
    const float* pa = x + ((size_t)b * C_DIM + (size_t)cs * C_PER_SLICE) * ch_stride
                        + (size_t)i * W_DIM + ja;
    const float* pb = pa + 256;

    float a0 = 0.f, a1 = 0.f, b0 = 0.f, b1 = 0.f;
    #pragma unroll 8
    for (int c = 0; c < C_PER_SLICE; c += 2) {
        const size_t o0 = (size_t)(c + 0) * ch_stride;
        const size_t o1 = (size_t)(c + 1) * ch_stride;
        a0 += __ldg(pa + o0);
        a1 += __ldg(pa + o1);
        if (hasb) {
            b0 += __ldg(pb + o0);
            b1 += __ldg(pb + o1);
        }
    }
    const float sa = a0 + a1;
    const float sb = b0 + b1;

    // Diagonal id and normalization for column ja
    {
        const int o = ja - i + 256;                    // 0..512
        const int off = o - 256;
        const int dlen = H_DIM - (off < 0 ? -off : off);
        atomicAdd(&out[b * N_OFF + o], sa / ((float)C_DIM * (float)dlen));
    }
    if (hasb) {
        const int o = jb - i + 256;
        const int off = o - 256;
        const int dlen = H_DIM - (off < 0 ? -off : off);
        atomicAdd(&out[b * N_OFF + o], sb / ((float)C_DIM * (float)dlen));
    }
}

extern "C" void kernel_launch(void* const* d_in, const int* in_sizes, int n_in,
                              void* d_out, int out_size) {
    const float* x = (const float*)d_in[0];
    float* out = (float*)d_out;

    zero_out_kernel<<<(OUT_ELEMS + 255) / 256, 256>>>(out, OUT_ELEMS);

    dim3 grid(H_DIM, B_DIM, C_SLICES);
    diag_pool_kernel<<<grid, 256>>>(x, out);
}

// round 3
// speedup vs baseline: 1.0431x; 1.0431x over previous
#include <cuda_runtime.h>
#include <cuda_bf16.h>

// DiagPooling: x [B=8, C=128, H=512, W=512] fp32 -> out [B, 1, 513] fp32
// out[b, 0, o] = (1 / (C * (512 - |o-256|))) * sum_{c, i} x[b, c, i, i + o - 256]
//
// Row i has valid columns [max(0,i-256), min(511,i+256)], width
// w(i) = 257 + min(i, 511-i). Pairing row p (p<256, width 257+p) with row
// p+256 (width 512-p) gives a CONSTANT combined width of 769 columns
// -> every block does identical work (no wave imbalance).
//
// Block = (pair p, batch b), 512 threads. Combined index u in [0,769):
//   u <  w1 (=257+p): row p,     j = u
//   u >= w1:          row p+256, j = u - 257
// Thread t handles item1 (u=t, always valid) and item2 (u=512+t, only
// t<257; always lands in row p+256). Full 128-channel register reduction,
// one pre-scaled atomicAdd per (thread,item) -> 1.57M REDG total.

#define B_DIM 8
#define C_DIM 128
#define H_DIM 512
#define W_DIM 512
#define N_OFF 513
#define OUT_ELEMS (B_DIM * N_OFF)

__global__ void zero_out_kernel(float* __restrict__ out, int n) {
    int idx = blockIdx.x * blockDim.x + threadIdx.x;
    if (idx < n) out[idx] = 0.0f;
}

__global__ __launch_bounds__(512) void diag_pool_kernel(
    const float* __restrict__ x, float* __restrict__ out)
{
    const int p = blockIdx.x;    // row pair 0..255 -> rows p and p+256
    const int b = blockIdx.y;    // batch 0..7
    const int t = threadIdx.x;   // 0..511

    const int w1 = 257 + p;      // width of row p

    // --- item 1: combined index u = t (always valid, 769 > 512) ---
    int row1, j1c, o1;
    if (t < w1) { row1 = p;       j1c = t;       o1 = t - p + 256; }
    else        { row1 = p + 256; j1c = t - 257; o1 = t - 257 - p; }

    // --- item 2: combined index u = 512 + t, valid iff t < 257 ---
    const bool has2 = (t < 257);
    const int row2 = p + 256;
    const int j2c  = t + 255;          // 512 + t - 257
    const int o2   = t + 255 - p;

    const size_t S = (size_t)H_DIM * W_DIM;   // channel stride
    const float* p1 = x + (size_t)b * C_DIM * S + (size_t)row1 * W_DIM + j1c;
    const float* p2 = x + (size_t)b * C_DIM * S + (size_t)row2 * W_DIM + j2c;

    float a0 = 0.f, a1 = 0.f, c0 = 0.f, c1 = 0.f;
    #pragma unroll 8
    for (int c = 0; c < C_DIM; c += 2) {
        const size_t q0 = (size_t)(c + 0) * S;
        const size_t q1 = (size_t)(c + 1) * S;
        a0 += __ldg(p1 + q0);
        a1 += __ldg(p1 + q1);
        if (has2) {
            c0 += __ldg(p2 + q0);
            c1 += __ldg(p2 + q1);
        }
    }
    const float s1 = a0 + a1;
    const float s2 = c0 + c1;

    // pre-scaled accumulation into out
    {
        const int off  = o1 - 256;
        const int dlen = H_DIM - (off < 0 ? -off : off);
        atomicAdd(&out[b * N_OFF + o1], s1 / ((float)C_DIM * (float)dlen));
    }
    if (has2) {
        const int off  = o2 - 256;
        const int dlen = H_DIM - (off < 0 ? -off : off);
        atomicAdd(&out[b * N_OFF + o2], s2 / ((float)C_DIM * (float)dlen));
    }
}

extern "C" void kernel_launch(void* const* d_in, const int* in_sizes, int n_in,
                              void* d_out, int out_size) {
    const float* x = (const float*)d_in[0];
    float* out = (float*)d_out;

    zero_out_kernel<<<(OUT_ELEMS + 255) / 256, 256>>>(out, OUT_ELEMS);

    dim3 grid(H_DIM / 2, B_DIM);   // 256 pairs x 8 batches = 2048 blocks
    diag_pool_kernel<<<grid, 512>>>(x, out);
}